// round 17
// baseline (speedup 1.0000x reference)
#include <cuda_runtime.h>
#include <cuda_bf16.h>
#include <cstddef>
#include <cstdint>

// Depthwise cross-correlation — R17: R12 compute (dup taps, q-pair MOVs,
// independent ffma2 chains) on R13's ALIGNED smem layout (row pitch 32,
// channel pitch 992) so every window load is an aligned LDS.64 for every
// channel. Kills the scalar-LDS + repack ALU tax of odd 961-based channels.
//   out[ch, oy, ox] = sum_{ky,kx} x[ch, oy+ky, ox+kx] * z[ch, ky, kx]
//   32768 channels, x: 31x31, z: 7x7, out: 25x25 (VALID, no flip)

#define NCHAN   32768
#define HX      31
#define HZ      7
#define HO      25
#define XSZ     961
#define ZSZ     49
#define OSZ     625
#define CPG     8                   // channels per group (2 per warp)
#define THREADS 128
#define CTAS_PER_SM 3
#define GRID    (152 * CTAS_PER_SM) // 456
#define NGROUPS (NCHAN / CPG)       // 4096 exactly
#define XTOT    ((size_t)NCHAN * XSZ)

#define RPITCH  32                  // smem row pitch (floats)
#define CHP     (HX * RPITCH)       // 992: smem channel pitch (aligned, even)
#define GXS     (CPG * CHP)         // 7936 floats per x buffer (31744 B)
#define GXF     (CPG * XSZ)         // 7688 gmem floats per group
#define GZ_FLOATS (CPG * ZSZ)       // 392
#define GZ_V4     (GZ_FLOATS / 4)   // 98

__device__ __forceinline__ void ffma2(float2& d, const float2& a, const float2& b) {
    asm("fma.rn.f32x2 %0, %1, %2, %0;"
        : "+l"(reinterpret_cast<unsigned long long&>(d))
        : "l"(reinterpret_cast<const unsigned long long&>(a)),
          "l"(reinterpret_cast<const unsigned long long&>(b)));
}

__device__ __forceinline__ void cpasync4(uint32_t saddr, const void* gaddr) {
    asm volatile("cp.async.ca.shared.global [%0], [%1], 4;"
                 :: "r"(saddr), "l"(gaddr) : "memory");
}
__device__ __forceinline__ void cpasync16(uint32_t saddr, const void* gaddr) {
    asm volatile("cp.async.cg.shared.global [%0], [%1], 16;"
                 :: "r"(saddr), "l"(gaddr) : "memory");
}
#define CP_COMMIT() asm volatile("cp.async.commit_group;" ::: "memory")
#define CP_WAIT1()  asm volatile("cp.async.wait_group 1;" ::: "memory")
#define CP_WAIT0()  asm volatile("cp.async.wait_group 0;" ::: "memory")

// Stage group g: gmem rows of 31 floats -> smem rows of 32 (col 31 = junk pad,
// only ever read by the dead .y lane of column 24). Warp w stages channels 2w
// (lanes 0-15) and 2w+1 (lanes 16-31); 4B cp.async streams stay coalesced.
template <bool CLAMP>
__device__ __forceinline__ void prefetch_group(
    int g, float* xs, float* zs,
    const float* __restrict__ x, const float* __restrict__ z, int tid)
{
    const int warp = tid >> 5, lane = tid & 31;
    const int h = lane >> 4, l16 = lane & 15;
    const int ch = 2 * warp + h;                       // 0..7

    const float* gsrc = x + (size_t)g * GXF + ch * XSZ + l16;
    uint32_t sdst = (uint32_t)__cvta_generic_to_shared(xs + ch * CHP + l16);
    const float* xlim = x + (XTOT - 1);

    #pragma unroll
    for (int m = 0; m < HX; ++m) {
        cpasync4(sdst, gsrc);                          // cols 0..15
        const float* g2 = gsrc + 16;                   // cols 16..30 (+1 junk)
        if (CLAMP && g2 > xlim) g2 = xlim;             // final-group tail only
        cpasync4(sdst + 64u, g2);
        gsrc += HX;                                    // next gmem row (31)
        sdst += (RPITCH * 4u);                         // next smem row (32)
    }

    if (tid < GZ_V4) {
        const float4* gz = reinterpret_cast<const float4*>(z) + (size_t)g * GZ_V4;
        const uint32_t sz = (uint32_t)__cvta_generic_to_shared(zs);
        cpasync16(sz + (uint32_t)tid * 16u, gz + tid);
    }
}

__device__ __forceinline__ void compute_group(
    int g, const float* __restrict__ xs, const float* __restrict__ zs,
    float* __restrict__ out, int lch, int l, bool active, bool store_hi)
{
    if (!active) return;                 // lanes 13..15 of each half-warp idle

    const float* xc = xs + lch * CHP;    // even base: aligned LDS.64 always
    const float* zc = zs + lch * ZSZ;
    const int col0 = 2 * l;              // output columns (col0, col0+1)

    // Taps duplicated into both f32x2 lanes: 49 float2 (98 regs), broadcast LDS.
    float2 kt[ZSZ];
    #pragma unroll
    for (int j = 0; j < ZSZ; ++j) {
        const float zv = zc[j];
        kt[j] = make_float2(zv, zv);
    }

    // Ring of 7 accumulators; lanes = the two adjacent output columns.
    float2 acc[HZ];
    #pragma unroll
    for (int i = 0; i < HZ; ++i) acc[i] = make_float2(0.0f, 0.0f);

    const float2* xb = reinterpret_cast<const float2*>(xc + col0);
    float* go = out + (size_t)(g * CPG + lch) * OSZ + col0;

    #pragma unroll
    for (int r = 0; r < HX; ++r) {
        // 4 aligned LDS.64: even pairs arrive pre-packed in register pairs.
        const float2 p0 = xb[r * (RPITCH / 2) + 0];    // (w0, w1)
        const float2 p1 = xb[r * (RPITCH / 2) + 1];    // (w2, w3)
        const float2 p2 = xb[r * (RPITCH / 2) + 2];    // (w4, w5)
        const float2 p3 = xb[r * (RPITCH / 2) + 3];    // (w6, w7) w7 dead lane

        const float2 q0 = make_float2(p0.y, p1.x);     // odd pairs: 6 MOVs
        const float2 q1 = make_float2(p1.y, p2.x);
        const float2 q2 = make_float2(p2.y, p3.x);

        #pragma unroll
        for (int ky = 0; ky < HZ; ++ky) {
            const int oy = r - ky;
            if (oy >= 0 && oy < HO) {
                const int s = oy % HZ;                 // const after unroll
                const float2* kz = &kt[ky * HZ];
                ffma2(acc[s], p0, kz[0]);
                ffma2(acc[s], q0, kz[1]);
                ffma2(acc[s], p1, kz[2]);
                ffma2(acc[s], q1, kz[3]);
                ffma2(acc[s], p2, kz[4]);
                ffma2(acc[s], q2, kz[5]);
                ffma2(acc[s], p3, kz[6]);
            }
        }

        if (r >= HZ - 1) {                             // output row r-6 done
            const int oy = r - (HZ - 1);
            const int s  = oy % HZ;
            go[oy * HO] = acc[s].x;
            if (store_hi) go[oy * HO + 1] = acc[s].y;
            acc[s] = make_float2(0.0f, 0.0f);
        }
    }
}

__global__ __launch_bounds__(THREADS, CTAS_PER_SM)
void dwxcorr_al(const float* __restrict__ z,
                const float* __restrict__ x,
                float* __restrict__ out) {
    extern __shared__ float smem[];
    float* xb0 = smem;
    float* xb1 = smem + GXS;
    float* zb0 = smem + 2 * GXS;
    float* zb1 = zb0 + GZ_FLOATS;

    const int tid  = threadIdx.x;
    const int warp = tid >> 5;
    const int lane = tid & 31;
    const int h    = lane >> 4;          // half-warp: channel select
    const int l    = lane & 15;          // lane within half-warp
    const int lch  = 2 * warp + h;       // local channel 0..7
    const bool active   = (l <= 12);     // 13 column-pair slots cover 25 cols
    const bool store_hi = (l < 12);      // lane 12: column 24 only

    int g = blockIdx.x;
    if (g < NGROUPS) {
        if (g == NGROUPS - 1) prefetch_group<true >(g, xb0, zb0, x, z, tid);
        else                  prefetch_group<false>(g, xb0, zb0, x, z, tid);
    }
    CP_COMMIT();

    int i = 0;
    for (; g < NGROUPS; g += GRID, ++i) {
        float* xc = (i & 1) ? xb1 : xb0;
        float* zc = (i & 1) ? zb1 : zb0;
        float* xn = (i & 1) ? xb0 : xb1;
        float* zn = (i & 1) ? zb0 : zb1;

        const int gn = g + GRID;
        if (gn < NGROUPS) {
            if (gn == NGROUPS - 1) prefetch_group<true >(gn, xn, zn, x, z, tid);
            else                   prefetch_group<false>(gn, xn, zn, x, z, tid);
            CP_COMMIT();
            CP_WAIT1();                               // current group landed
        } else {
            CP_WAIT0();
        }
        __syncthreads();

        compute_group(g, xc, zc, out, lch, l, active, store_hi);

        __syncthreads();                              // done reading xc/zc
    }
}

extern "C" void kernel_launch(void* const* d_in, const int* in_sizes, int n_in,
                              void* d_out, int out_size) {
    // metadata order: d_in[0] = z_f [128,256,7,7], d_in[1] = x_f [128,256,31,31]
    const float* z = (const float*)d_in[0];
    const float* x = (const float*)d_in[1];
    float* out = (float*)d_out;

    const size_t smem = (size_t)(2 * GXS + 2 * GZ_FLOATS) * sizeof(float); // 66624 B
    cudaFuncSetAttribute(dwxcorr_al,
                         cudaFuncAttributeMaxDynamicSharedMemorySize, (int)smem);
    dwxcorr_al<<<GRID, THREADS, smem>>>(z, x, out);
}